// round 8
// baseline (speedup 1.0000x reference)
#include <cuda_runtime.h>
#include <cuda_bf16.h>
#include <cstdint>

#define BB 4
#define SS 2048
#define HH 1024

typedef __nv_bfloat16  bf16;
typedef __nv_bfloat162 bf162;

// ---------------- scratch (static device globals; no allocation) ----------------
__device__ bf16 g_xhi[(size_t)BB*SS*HH], g_xlo[(size_t)BB*SS*HH];   // X planes   [bs][h]
__device__ bf16 g_whi[(size_t)3*HH*HH],  g_wlo[(size_t)3*HH*HH];    // Wq|Wk|Wv   [o][h]
__device__ bf16 g_qhi[(size_t)BB*SS*HH], g_qlo[(size_t)BB*SS*HH];   // q planes   [bs][h]
__device__ bf16 g_khi[(size_t)BB*SS*HH], g_klo[(size_t)BB*SS*HH];   // k planes   [bs][h]
__device__ bf16 g_vthi[(size_t)BB*HH*SS],g_vtlo[(size_t)BB*HH*SS];  // v^T planes [b][h][s]
__device__ float g_s[(size_t)BB*SS*SS];                             // scores fp32
__device__ bf16 g_phi[(size_t)BB*SS*SS], g_plo[(size_t)BB*SS*SS];   // prob planes [b][q][k]

// ---------------- low-level helpers ----------------
static __device__ __forceinline__ void mma_bf16(float* d, const uint32_t* a, const uint32_t* b) {
    asm volatile(
        "mma.sync.aligned.m16n8k16.row.col.f32.bf16.bf16.f32 "
        "{%0,%1,%2,%3}, {%4,%5,%6,%7}, {%8,%9}, {%0,%1,%2,%3};\n"
        : "+f"(d[0]), "+f"(d[1]), "+f"(d[2]), "+f"(d[3])
        : "r"(a[0]), "r"(a[1]), "r"(a[2]), "r"(a[3]), "r"(b[0]), "r"(b[1]));
}

static __device__ __forceinline__ uint32_t smem_u32(const void* p) {
    return (uint32_t)__cvta_generic_to_shared(p);
}
static __device__ __forceinline__ void cp16(uint32_t dst, const void* src) {
    asm volatile("cp.async.cg.shared.global [%0], [%1], 16;\n" :: "r"(dst), "l"(src));
}
static __device__ __forceinline__ void cp_commit() { asm volatile("cp.async.commit_group;\n"); }
static __device__ __forceinline__ void cp_wait0()  { asm volatile("cp.async.wait_group 0;\n"); }

static __device__ __forceinline__ void ldm_x4(uint32_t* r, uint32_t addr) {
    asm volatile("ldmatrix.sync.aligned.m8n8.x4.shared.b16 {%0,%1,%2,%3}, [%4];\n"
        : "=r"(r[0]), "=r"(r[1]), "=r"(r[2]), "=r"(r[3]) : "r"(addr));
}
static __device__ __forceinline__ void ldm_x2(uint32_t* r, uint32_t addr) {
    asm volatile("ldmatrix.sync.aligned.m8n8.x2.shared.b16 {%0,%1}, [%2];\n"
        : "=r"(r[0]), "=r"(r[1]) : "r"(addr));
}

static __device__ __forceinline__ void split2(float x, float y, bf162& h2, bf162& l2) {
    bf16 hx = __float2bfloat16_rn(x);
    bf16 hy = __float2bfloat16_rn(y);
    h2 = __halves2bfloat162(hx, hy);
    l2 = __halves2bfloat162(__float2bfloat16_rn(x - __bfloat162float(hx)),
                            __float2bfloat16_rn(y - __bfloat162float(hy)));
}

// fast exp via degree-5 exp2 polynomial (FMA pipe, no MUFU); rel err ~1e-7
static __device__ __forceinline__ float fast_exp(float x) {
    float t = x * 1.4426950408889634f;
    float r = rintf(t);
    float f = t - r;
    float p = 1.33336498e-3f;
    p = fmaf(p, f, 9.61597636e-3f);
    p = fmaf(p, f, 5.55036440e-2f);
    p = fmaf(p, f, 2.40226462e-1f);
    p = fmaf(p, f, 6.93147182e-1f);
    p = fmaf(p, f, 1.0f);
    int e = (int)r;
    e = e < -126 ? -126 : e;
    return p * __int_as_float((e + 127) << 23);
}

// ---------------- GEMM core: C[128,128] = A[128,K] * B[128,K]^T, bf16x3 fp32-emulated ----
// Operands are pre-split bf16 hi/lo planes, K-contiguous. cp.async 2-stage double buffer.
#define KTILE 32
#define LDT   40                        // smem row stride in bf16 elems (80 B)
#define PLANE_B (128 * LDT * 2)         // 10240 B per plane
#define STAGE_B (4 * PLANE_B)           // 40960 B per stage
#define SMEM_BYTES (2 * STAGE_B)        // 81920 B total

static __device__ __forceinline__ void issue_tile(const bf16* __restrict__ g, int ld, int k0,
                                                  uint32_t sdst, int tid) {
#pragma unroll
    for (int i = 0; i < 2; i++) {
        int idx = tid * 2 + i;          // 0..511
        int row = idx >> 2;             // 128 rows
        int ch  = idx & 3;              // 4 x 16B chunks per 64B row
        cp16(sdst + row * 80 + ch * 16, g + (size_t)row * ld + k0 + ch * 8);
    }
}

static __device__ __forceinline__ void gemm_core(
    const bf16* __restrict__ Ahi, const bf16* __restrict__ Alo, int lda,
    const bf16* __restrict__ Bhi, const bf16* __restrict__ Blo, int ldb,
    int K, char* sm, float acc[4][4][4]) {
    const int tid  = threadIdx.x;
    const int lane = tid & 31;
    const int warp = tid >> 5;
    const int mbase = (warp >> 2) * 64;
    const int nbase = (warp & 3) * 32;
    const uint32_t s0 = smem_u32(sm);

    // ldmatrix per-lane byte offsets (within plane)
    const uint32_t aoff = (uint32_t)(((lane & 7) + ((lane >> 3) & 1) * 8 + mbase) * 80
                                     + (lane >> 4) * 16);
    const int l16 = lane & 15;
    const uint32_t boff = (uint32_t)(((l16 & 7) + nbase) * 80 + ((l16 >> 3) & 1) * 16);

    const int n = K / KTILE;
    issue_tile(Ahi, lda, 0, s0 + 0 * PLANE_B, tid);
    issue_tile(Alo, lda, 0, s0 + 1 * PLANE_B, tid);
    issue_tile(Bhi, ldb, 0, s0 + 2 * PLANE_B, tid);
    issue_tile(Blo, ldb, 0, s0 + 3 * PLANE_B, tid);
    cp_commit();

    for (int it = 0; it < n; ++it) {
        cp_wait0();
        __syncthreads();
        if (it + 1 < n) {
            uint32_t sb = s0 + (uint32_t)((it + 1) & 1) * STAGE_B;
            int k0 = (it + 1) * KTILE;
            issue_tile(Ahi, lda, k0, sb + 0 * PLANE_B, tid);
            issue_tile(Alo, lda, k0, sb + 1 * PLANE_B, tid);
            issue_tile(Bhi, ldb, k0, sb + 2 * PLANE_B, tid);
            issue_tile(Blo, ldb, k0, sb + 3 * PLANE_B, tid);
            cp_commit();
        }
        uint32_t st = s0 + (uint32_t)(it & 1) * STAGE_B;
#pragma unroll
        for (int kk = 0; kk < 2; ++kk) {
            uint32_t kb = (uint32_t)kk * 32;   // 16 bf16 = 32 bytes
            uint32_t bh[4][2], bl[4][2];
#pragma unroll
            for (int in = 0; in < 4; in++) {
                ldm_x2(bh[in], st + 2 * PLANE_B + boff + in * 8 * 80 + kb);
                ldm_x2(bl[in], st + 3 * PLANE_B + boff + in * 8 * 80 + kb);
            }
#pragma unroll
            for (int im = 0; im < 4; im++) {
                uint32_t ah[4], al[4];
                ldm_x4(ah, st + 0 * PLANE_B + aoff + im * 16 * 80 + kb);
                ldm_x4(al, st + 1 * PLANE_B + aoff + im * 16 * 80 + kb);
#pragma unroll
                for (int in = 0; in < 4; in++) {
                    mma_bf16(acc[im][in], ah, bh[in]);   // hi*hi
                    mma_bf16(acc[im][in], ah, bl[in]);   // hi*lo
                    mma_bf16(acc[im][in], al, bh[in]);   // lo*hi
                }
            }
        }
        // no trailing sync: next iteration's sync (after wait) protects both buffers
    }
}

#define ZERO_ACC(acc) do {                                   \
    _Pragma("unroll") for (int _i = 0; _i < 4; _i++)         \
    _Pragma("unroll") for (int _j = 0; _j < 4; _j++)         \
    _Pragma("unroll") for (int _r = 0; _r < 4; _r++)         \
        acc[_i][_j][_r] = 0.0f;                              \
} while (0)

// ---------------- Stage 0: fp32 -> bf16 hi/lo plane conversion ----------------
__global__ __launch_bounds__(256) void cvt_kernel(const float4* __restrict__ src,
                                                  bf162* __restrict__ hi,
                                                  bf162* __restrict__ lo, int n4) {
    int i = blockIdx.x * blockDim.x + threadIdx.x;
    if (i < n4) {
        float4 f = src[i];
        bf162 h0, l0, h1, l1;
        split2(f.x, f.y, h0, l0);
        split2(f.z, f.w, h1, l1);
        hi[i * 2] = h0; hi[i * 2 + 1] = h1;
        lo[i * 2] = l0; lo[i * 2 + 1] = l1;
    }
}

// ---------------- Stage 1: fused QKV projection ----------------
// grid = (8, 64, 3). z selects {q,k,v}. v is transposed via smem -> coalesced plane stores.
__global__ __launch_bounds__(256, 2) void qkv_kernel(const float* __restrict__ bq,
                                                     const float* __restrict__ bk,
                                                     const float* __restrict__ bv) {
    extern __shared__ char sm[];
    const int z = blockIdx.z, bm = blockIdx.y, bn = blockIdx.x;
    const float* bias = (z == 0) ? bq : ((z == 1) ? bk : bv);

    float acc[4][4][4];
    ZERO_ACC(acc);
    gemm_core(g_xhi + (size_t)bm * 128 * HH, g_xlo + (size_t)bm * 128 * HH, HH,
              g_whi + (size_t)z * HH * HH + (size_t)bn * 128 * HH,
              g_wlo + (size_t)z * HH * HH + (size_t)bn * 128 * HH, HH,
              HH, sm, acc);

    const int lane = threadIdx.x & 31;
    const int warp = threadIdx.x >> 5;
    const int mbase = (warp >> 2) * 64;
    const int nbase = (warp & 3) * 32;
    const int gr = lane >> 2;
    const int gc = (lane & 3) << 1;

    if (z < 2) {
        bf16* ohi = (z == 0) ? g_qhi : g_khi;
        bf16* olo = (z == 0) ? g_qlo : g_klo;
#pragma unroll
        for (int im = 0; im < 4; im++) {
#pragma unroll
            for (int in = 0; in < 4; in++) {
                int row = bm * 128 + mbase + im * 16 + gr;
                int col = bn * 128 + nbase + in * 8 + gc;
                float b0 = bias[col], b1 = bias[col + 1];
                bf162 h2, l2;
                split2(acc[im][in][0] + b0, acc[im][in][1] + b1, h2, l2);
                *reinterpret_cast<bf162*>(&ohi[(size_t)row * HH + col]) = h2;
                *reinterpret_cast<bf162*>(&olo[(size_t)row * HH + col]) = l2;
                split2(acc[im][in][2] + b0, acc[im][in][3] + b1, h2, l2);
                *reinterpret_cast<bf162*>(&ohi[(size_t)(row + 8) * HH + col]) = h2;
                *reinterpret_cast<bf162*>(&olo[(size_t)(row + 8) * HH + col]) = l2;
            }
        }
    } else {
        // transpose v tile through smem, then coalesced hi/lo stores into [b][h][s] planes
        __syncthreads();
        float* ts = reinterpret_cast<float*>(sm);   // 128 x 129 fp32 = 66048 B
#pragma unroll
        for (int im = 0; im < 4; im++) {
#pragma unroll
            for (int in = 0; in < 4; in++) {
                int r0 = mbase + im * 16 + gr;
                int c0 = nbase + in * 8 + gc;
                float b0 = bias[bn * 128 + c0], b1 = bias[bn * 128 + c0 + 1];
                ts[r0 * 129 + c0]           = acc[im][in][0] + b0;
                ts[r0 * 129 + c0 + 1]       = acc[im][in][1] + b1;
                ts[(r0 + 8) * 129 + c0]     = acc[im][in][2] + b0;
                ts[(r0 + 8) * 129 + c0 + 1] = acc[im][in][3] + b1;
            }
        }
        __syncthreads();
        const int b = (bm * 128) >> 11;
        const int sbase = (bm * 128) & (SS - 1);
#pragma unroll
        for (int hr = 0; hr < 16; hr++) {
            int hl = warp * 16 + hr;                         // local h row 0..127
            size_t obase = ((size_t)b * HH + bn * 128 + hl) * SS + sbase;
#pragma unroll
            for (int pass = 0; pass < 2; pass++) {
                int sl = pass * 64 + lane * 2;
                bf162 h2, l2;
                split2(ts[sl * 129 + hl], ts[(sl + 1) * 129 + hl], h2, l2);
                *reinterpret_cast<bf162*>(&g_vthi[obase + sl]) = h2;
                *reinterpret_cast<bf162*>(&g_vtlo[obase + sl]) = l2;
            }
        }
    }
}

// ---------------- Stage 2: scores = q k^T * scale + attn_mask + pw*prosody ----------------
__global__ __launch_bounds__(256, 2) void scores_kernel(const float* __restrict__ am,
                                                        const float* __restrict__ pm,
                                                        const float* __restrict__ pwp) {
    extern __shared__ char sm[];
    const int b = blockIdx.z, bm = blockIdx.y, bn = blockIdx.x;

    float acc[4][4][4];
    ZERO_ACC(acc);
    const size_t ao = (size_t)(b * SS + bm * 128) * HH;
    const size_t bo = (size_t)(b * SS + bn * 128) * HH;
    gemm_core(g_qhi + ao, g_qlo + ao, HH, g_khi + bo, g_klo + bo, HH, HH, sm, acc);

    const float pw = __ldg(pwp);
    const float scale = 0.03125f;   // 1/sqrt(1024)
    const int lane = threadIdx.x & 31;
    const int warp = threadIdx.x >> 5;
    const int mbase = (warp >> 2) * 64;
    const int nbase = (warp & 3) * 32;
    const int gr = lane >> 2;
    const int gc = (lane & 3) << 1;

#pragma unroll
    for (int im = 0; im < 4; im++) {
#pragma unroll
        for (int in = 0; in < 4; in++) {
            int row = bm * 128 + mbase + im * 16 + gr;
            int col = bn * 128 + nbase + in * 8 + gc;
#pragma unroll
            for (int half = 0; half < 2; half++) {
                int r = row + half * 8;
                size_t off = ((size_t)b * SS + r) * SS + col;
                float2 amv = *reinterpret_cast<const float2*>(&am[off]);
                float2 pmv = *reinterpret_cast<const float2*>(&pm[off]);
                float v0 = fmaf(acc[im][in][half * 2 + 0], scale, fmaf(pw, pmv.x, amv.x));
                float v1 = fmaf(acc[im][in][half * 2 + 1], scale, fmaf(pw, pmv.y, amv.y));
                *reinterpret_cast<float2*>(&g_s[off]) = make_float2(v0, v1);
            }
        }
    }
}

// ---------------- Stage 3: row softmax -> bf16 hi/lo prob planes ----------------
__global__ __launch_bounds__(256) void softmax_kernel() {
    const size_t rid = blockIdx.x;
    const float* row = g_s + rid * SS;
    const int tid = threadIdx.x;
    const int lane = tid & 31;
    const int warp = tid >> 5;
    const float4* rv = reinterpret_cast<const float4*>(row);
    float4 a = rv[tid];
    float4 c = rv[tid + 256];

    float m = fmaxf(fmaxf(fmaxf(a.x, a.y), fmaxf(a.z, a.w)),
                    fmaxf(fmaxf(c.x, c.y), fmaxf(c.z, c.w)));
#pragma unroll
    for (int o = 16; o > 0; o >>= 1) m = fmaxf(m, __shfl_xor_sync(0xffffffffu, m, o));
    __shared__ float smax[8], ssum[8];
    if (lane == 0) smax[warp] = m;
    __syncthreads();
    m = smax[0];
#pragma unroll
    for (int w = 1; w < 8; w++) m = fmaxf(m, smax[w]);

    a.x = fast_exp(a.x - m); a.y = fast_exp(a.y - m);
    a.z = fast_exp(a.z - m); a.w = fast_exp(a.w - m);
    c.x = fast_exp(c.x - m); c.y = fast_exp(c.y - m);
    c.z = fast_exp(c.z - m); c.w = fast_exp(c.w - m);
    float s = a.x + a.y + a.z + a.w + c.x + c.y + c.z + c.w;
#pragma unroll
    for (int o = 16; o > 0; o >>= 1) s += __shfl_xor_sync(0xffffffffu, s, o);
    if (lane == 0) ssum[warp] = s;
    __syncthreads();
    s = ssum[0];
#pragma unroll
    for (int w = 1; w < 8; w++) s += ssum[w];
    const float inv = 1.0f / s;

    bf162* ph = reinterpret_cast<bf162*>(g_phi);
    bf162* pl = reinterpret_cast<bf162*>(g_plo);
    size_t base = rid * (SS / 2) + tid * 2;
    bf162 h2, l2;
    split2(a.x * inv, a.y * inv, h2, l2); ph[base] = h2;       pl[base] = l2;
    split2(a.z * inv, a.w * inv, h2, l2); ph[base + 1] = h2;   pl[base + 1] = l2;
    split2(c.x * inv, c.y * inv, h2, l2); ph[base + 512] = h2; pl[base + 512] = l2;
    split2(c.z * inv, c.w * inv, h2, l2); ph[base + 513] = h2; pl[base + 513] = l2;
}

// ---------------- Stage 4: context = probs @ v ----------------
__global__ __launch_bounds__(256, 2) void pv_kernel(float* __restrict__ out) {
    extern __shared__ char sm[];
    const int b = blockIdx.z, bm = blockIdx.y, bn = blockIdx.x;

    float acc[4][4][4];
    ZERO_ACC(acc);
    const size_t ao = (size_t)(b * SS + bm * 128) * SS;
    const size_t bo = ((size_t)b * HH + bn * 128) * SS;
    gemm_core(g_phi + ao, g_plo + ao, SS, g_vthi + bo, g_vtlo + bo, SS, SS, sm, acc);

    const int lane = threadIdx.x & 31;
    const int warp = threadIdx.x >> 5;
    const int mbase = (warp >> 2) * 64;
    const int nbase = (warp & 3) * 32;
    const int gr = lane >> 2;
    const int gc = (lane & 3) << 1;

#pragma unroll
    for (int im = 0; im < 4; im++) {
#pragma unroll
        for (int in = 0; in < 4; in++) {
            int row = bm * 128 + mbase + im * 16 + gr;
            int col = bn * 128 + nbase + in * 8 + gc;
            size_t o0 = ((size_t)b * SS + row) * HH + col;
            size_t o1 = ((size_t)b * SS + row + 8) * HH + col;
            *reinterpret_cast<float2*>(&out[o0]) = make_float2(acc[im][in][0], acc[im][in][1]);
            *reinterpret_cast<float2*>(&out[o1]) = make_float2(acc[im][in][2], acc[im][in][3]);
        }
    }
}

// ---------------- launch ----------------
extern "C" void kernel_launch(void* const* d_in, const int* in_sizes, int n_in,
                              void* d_out, int out_size) {
    (void)in_sizes; (void)n_in; (void)out_size;
    const float* X  = (const float*)d_in[0];
    const float* am = (const float*)d_in[1];
    const float* pm = (const float*)d_in[2];
    const float* Wq = (const float*)d_in[3];
    const float* bq = (const float*)d_in[4];
    const float* Wk = (const float*)d_in[5];
    const float* bk = (const float*)d_in[6];
    const float* Wv = (const float*)d_in[7];
    const float* bv = (const float*)d_in[8];
    const float* pw = (const float*)d_in[9];
    float* out = (float*)d_out;

    cudaFuncSetAttribute(qkv_kernel,    cudaFuncAttributeMaxDynamicSharedMemorySize, SMEM_BYTES);
    cudaFuncSetAttribute(scores_kernel, cudaFuncAttributeMaxDynamicSharedMemorySize, SMEM_BYTES);
    cudaFuncSetAttribute(pv_kernel,     cudaFuncAttributeMaxDynamicSharedMemorySize, SMEM_BYTES);

    // resolve device-global plane addresses (host-side symbol lookup not needed: kernels
    // reference the globals directly; conversion kernels get raw pointers via kernels' own refs)
    {
        // X planes: 8M floats -> 2M float4
        int n4 = (BB * SS * HH) / 4;
        // obtain device pointers to the __device__ arrays for the cvt kernel
        bf162* xhi2; bf162* xlo2; bf162* whi2; bf162* wlo2;
        cudaGetSymbolAddress((void**)&xhi2, g_xhi);
        cudaGetSymbolAddress((void**)&xlo2, g_xlo);
        cudaGetSymbolAddress((void**)&whi2, g_whi);
        cudaGetSymbolAddress((void**)&wlo2, g_wlo);
        cvt_kernel<<<(n4 + 255) / 256, 256>>>((const float4*)X, xhi2, xlo2, n4);
        // W planes: Wq|Wk|Wv are three separate inputs -> three sub-launches into one array
        int w4 = (HH * HH) / 4;
        cvt_kernel<<<(w4 + 255) / 256, 256>>>((const float4*)Wq, whi2,                 wlo2,                 w4);
        cvt_kernel<<<(w4 + 255) / 256, 256>>>((const float4*)Wk, whi2 + (size_t)HH*HH/2, wlo2 + (size_t)HH*HH/2, w4);
        cvt_kernel<<<(w4 + 255) / 256, 256>>>((const float4*)Wv, whi2 + (size_t)HH*HH,   wlo2 + (size_t)HH*HH,   w4);
    }

    qkv_kernel<<<dim3(HH / 128, (BB * SS) / 128, 3), 256, SMEM_BYTES>>>(bq, bk, bv);
    scores_kernel<<<dim3(SS / 128, SS / 128, BB), 256, SMEM_BYTES>>>(am, pm, pw);
    softmax_kernel<<<BB * SS, 256>>>();
    pv_kernel<<<dim3(HH / 128, SS / 128, BB), 256, SMEM_BYTES>>>(out);
}

// round 9
// speedup vs baseline: 1.0020x; 1.0020x over previous
#include <cuda_runtime.h>
#include <cuda_bf16.h>
#include <cstdint>

#define BB 4
#define SS 2048
#define HH 1024

typedef __nv_bfloat16  bf16;
typedef __nv_bfloat162 bf162;

// ---------------- scratch (static device globals; no allocation) ----------------
__device__ bf16 g_xhi[(size_t)BB*SS*HH], g_xlo[(size_t)BB*SS*HH];   // X planes   [bs][h]
__device__ bf16 g_whi[(size_t)3*HH*HH],  g_wlo[(size_t)3*HH*HH];    // Wq|Wk|Wv   [o][h]
__device__ bf16 g_qhi[(size_t)BB*SS*HH], g_qlo[(size_t)BB*SS*HH];   // q planes   [bs][h]
__device__ bf16 g_khi[(size_t)BB*SS*HH], g_klo[(size_t)BB*SS*HH];   // k planes   [bs][h]
__device__ bf16 g_vthi[(size_t)BB*HH*SS],g_vtlo[(size_t)BB*HH*SS];  // v^T planes [b][h][s]
__device__ float g_s[(size_t)BB*SS*SS];                             // scores fp32
__device__ bf16 g_phi[(size_t)BB*SS*SS], g_plo[(size_t)BB*SS*SS];   // prob planes [b][q][k]

// ---------------- low-level helpers ----------------
static __device__ __forceinline__ void mma_bf16(float* d, const uint32_t* a, const uint32_t* b) {
    asm volatile(
        "mma.sync.aligned.m16n8k16.row.col.f32.bf16.bf16.f32 "
        "{%0,%1,%2,%3}, {%4,%5,%6,%7}, {%8,%9}, {%0,%1,%2,%3};\n"
        : "+f"(d[0]), "+f"(d[1]), "+f"(d[2]), "+f"(d[3])
        : "r"(a[0]), "r"(a[1]), "r"(a[2]), "r"(a[3]), "r"(b[0]), "r"(b[1]));
}

static __device__ __forceinline__ uint32_t smem_u32(const void* p) {
    return (uint32_t)__cvta_generic_to_shared(p);
}
static __device__ __forceinline__ void cp16(uint32_t dst, const void* src) {
    asm volatile("cp.async.cg.shared.global [%0], [%1], 16;\n" :: "r"(dst), "l"(src));
}
static __device__ __forceinline__ void cp_commit() { asm volatile("cp.async.commit_group;\n"); }
static __device__ __forceinline__ void cp_wait0()  { asm volatile("cp.async.wait_group 0;\n"); }

static __device__ __forceinline__ void ldm_x4(uint32_t* r, uint32_t addr) {
    asm volatile("ldmatrix.sync.aligned.m8n8.x4.shared.b16 {%0,%1,%2,%3}, [%4];\n"
        : "=r"(r[0]), "=r"(r[1]), "=r"(r[2]), "=r"(r[3]) : "r"(addr));
}
static __device__ __forceinline__ void ldm_x2(uint32_t* r, uint32_t addr) {
    asm volatile("ldmatrix.sync.aligned.m8n8.x2.shared.b16 {%0,%1}, [%2];\n"
        : "=r"(r[0]), "=r"(r[1]) : "r"(addr));
}

static __device__ __forceinline__ void split2(float x, float y, bf162& h2, bf162& l2) {
    bf16 hx = __float2bfloat16_rn(x);
    bf16 hy = __float2bfloat16_rn(y);
    h2 = __halves2bfloat162(hx, hy);
    l2 = __halves2bfloat162(__float2bfloat16_rn(x - __bfloat162float(hx)),
                            __float2bfloat16_rn(y - __bfloat162float(hy)));
}

// fast exp via degree-5 exp2 polynomial (FMA pipe, no MUFU); rel err ~1e-7
static __device__ __forceinline__ float fast_exp(float x) {
    float t = x * 1.4426950408889634f;
    float r = rintf(t);
    float f = t - r;
    float p = 1.33336498e-3f;
    p = fmaf(p, f, 9.61597636e-3f);
    p = fmaf(p, f, 5.55036440e-2f);
    p = fmaf(p, f, 2.40226462e-1f);
    p = fmaf(p, f, 6.93147182e-1f);
    p = fmaf(p, f, 1.0f);
    int e = (int)r;
    e = e < -126 ? -126 : e;
    return p * __int_as_float((e + 127) << 23);
}

// ---------------- GEMM core: C[128,128] = A[128,K] * B[128,K]^T, bf16x3 fp32-emulated ----
// Operands are pre-split bf16 hi/lo planes, K-contiguous. cp.async 2-stage double buffer.
#define KTILE 32
#define LDT   40                        // smem row stride in bf16 elems (80 B)
#define PLANE_B (128 * LDT * 2)         // 10240 B per plane
#define STAGE_B (4 * PLANE_B)           // 40960 B per stage
#define SMEM_BYTES (2 * STAGE_B)        // 81920 B total

static __device__ __forceinline__ void issue_tile(const bf16* __restrict__ g, int ld, int k0,
                                                  uint32_t sdst, int tid) {
#pragma unroll
    for (int i = 0; i < 2; i++) {
        int idx = tid * 2 + i;          // 0..511
        int row = idx >> 2;             // 128 rows
        int ch  = idx & 3;              // 4 x 16B chunks per 64B row
        cp16(sdst + row * 80 + ch * 16, g + (size_t)row * ld + k0 + ch * 8);
    }
}

static __device__ __forceinline__ void gemm_core(
    const bf16* __restrict__ Ahi, const bf16* __restrict__ Alo, int lda,
    const bf16* __restrict__ Bhi, const bf16* __restrict__ Blo, int ldb,
    int K, char* sm, float acc[4][4][4]) {
    const int tid  = threadIdx.x;
    const int lane = tid & 31;
    const int warp = tid >> 5;
    const int mbase = (warp >> 2) * 64;
    const int nbase = (warp & 3) * 32;
    const uint32_t s0 = smem_u32(sm);

    // ldmatrix per-lane byte offsets (within plane)
    const uint32_t aoff = (uint32_t)(((lane & 7) + ((lane >> 3) & 1) * 8 + mbase) * 80
                                     + (lane >> 4) * 16);
    const int l16 = lane & 15;
    const uint32_t boff = (uint32_t)(((l16 & 7) + nbase) * 80 + ((l16 >> 3) & 1) * 16);

    const int n = K / KTILE;
    issue_tile(Ahi, lda, 0, s0 + 0 * PLANE_B, tid);
    issue_tile(Alo, lda, 0, s0 + 1 * PLANE_B, tid);
    issue_tile(Bhi, ldb, 0, s0 + 2 * PLANE_B, tid);
    issue_tile(Blo, ldb, 0, s0 + 3 * PLANE_B, tid);
    cp_commit();

    for (int it = 0; it < n; ++it) {
        cp_wait0();
        __syncthreads();
        if (it + 1 < n) {
            uint32_t sb = s0 + (uint32_t)((it + 1) & 1) * STAGE_B;
            int k0 = (it + 1) * KTILE;
            issue_tile(Ahi, lda, k0, sb + 0 * PLANE_B, tid);
            issue_tile(Alo, lda, k0, sb + 1 * PLANE_B, tid);
            issue_tile(Bhi, ldb, k0, sb + 2 * PLANE_B, tid);
            issue_tile(Blo, ldb, k0, sb + 3 * PLANE_B, tid);
            cp_commit();
        }
        uint32_t st = s0 + (uint32_t)(it & 1) * STAGE_B;
#pragma unroll
        for (int kk = 0; kk < 2; ++kk) {
            uint32_t kb = (uint32_t)kk * 32;   // 16 bf16 = 32 bytes
            uint32_t bh[4][2], bl[4][2];
#pragma unroll
            for (int in = 0; in < 4; in++) {
                ldm_x2(bh[in], st + 2 * PLANE_B + boff + in * 8 * 80 + kb);
                ldm_x2(bl[in], st + 3 * PLANE_B + boff + in * 8 * 80 + kb);
            }
#pragma unroll
            for (int im = 0; im < 4; im++) {
                uint32_t ah[4], al[4];
                ldm_x4(ah, st + 0 * PLANE_B + aoff + im * 16 * 80 + kb);
                ldm_x4(al, st + 1 * PLANE_B + aoff + im * 16 * 80 + kb);
#pragma unroll
                for (int in = 0; in < 4; in++) {
                    mma_bf16(acc[im][in], ah, bh[in]);   // hi*hi
                    mma_bf16(acc[im][in], ah, bl[in]);   // hi*lo
                    mma_bf16(acc[im][in], al, bh[in]);   // lo*hi
                }
            }
        }
        // no trailing sync: next iteration's sync (after wait) protects both buffers
    }
}

#define ZERO_ACC(acc) do {                                   \
    _Pragma("unroll") for (int _i = 0; _i < 4; _i++)         \
    _Pragma("unroll") for (int _j = 0; _j < 4; _j++)         \
    _Pragma("unroll") for (int _r = 0; _r < 4; _r++)         \
        acc[_i][_j][_r] = 0.0f;                              \
} while (0)

// ---------------- Stage 0: fp32 -> bf16 hi/lo plane conversion ----------------
__global__ __launch_bounds__(256) void cvt_kernel(const float4* __restrict__ src,
                                                  bf162* __restrict__ hi,
                                                  bf162* __restrict__ lo, int n4) {
    int i = blockIdx.x * blockDim.x + threadIdx.x;
    if (i < n4) {
        float4 f = src[i];
        bf162 h0, l0, h1, l1;
        split2(f.x, f.y, h0, l0);
        split2(f.z, f.w, h1, l1);
        hi[i * 2] = h0; hi[i * 2 + 1] = h1;
        lo[i * 2] = l0; lo[i * 2 + 1] = l1;
    }
}

// ---------------- Stage 1: fused QKV projection ----------------
// grid = (8, 64, 3). z selects {q,k,v}. v is transposed via smem -> coalesced plane stores.
__global__ __launch_bounds__(256, 2) void qkv_kernel(const float* __restrict__ bq,
                                                     const float* __restrict__ bk,
                                                     const float* __restrict__ bv) {
    extern __shared__ char sm[];
    const int z = blockIdx.z, bm = blockIdx.y, bn = blockIdx.x;
    const float* bias = (z == 0) ? bq : ((z == 1) ? bk : bv);

    float acc[4][4][4];
    ZERO_ACC(acc);
    gemm_core(g_xhi + (size_t)bm * 128 * HH, g_xlo + (size_t)bm * 128 * HH, HH,
              g_whi + (size_t)z * HH * HH + (size_t)bn * 128 * HH,
              g_wlo + (size_t)z * HH * HH + (size_t)bn * 128 * HH, HH,
              HH, sm, acc);

    const int lane = threadIdx.x & 31;
    const int warp = threadIdx.x >> 5;
    const int mbase = (warp >> 2) * 64;
    const int nbase = (warp & 3) * 32;
    const int gr = lane >> 2;
    const int gc = (lane & 3) << 1;

    if (z < 2) {
        bf16* ohi = (z == 0) ? g_qhi : g_khi;
        bf16* olo = (z == 0) ? g_qlo : g_klo;
#pragma unroll
        for (int im = 0; im < 4; im++) {
#pragma unroll
            for (int in = 0; in < 4; in++) {
                int row = bm * 128 + mbase + im * 16 + gr;
                int col = bn * 128 + nbase + in * 8 + gc;
                float b0 = bias[col], b1 = bias[col + 1];
                bf162 h2, l2;
                split2(acc[im][in][0] + b0, acc[im][in][1] + b1, h2, l2);
                *reinterpret_cast<bf162*>(&ohi[(size_t)row * HH + col]) = h2;
                *reinterpret_cast<bf162*>(&olo[(size_t)row * HH + col]) = l2;
                split2(acc[im][in][2] + b0, acc[im][in][3] + b1, h2, l2);
                *reinterpret_cast<bf162*>(&ohi[(size_t)(row + 8) * HH + col]) = h2;
                *reinterpret_cast<bf162*>(&olo[(size_t)(row + 8) * HH + col]) = l2;
            }
        }
    } else {
        // transpose v tile through smem, then coalesced hi/lo stores into [b][h][s] planes
        __syncthreads();
        float* ts = reinterpret_cast<float*>(sm);   // 128 x 129 fp32 = 66048 B
#pragma unroll
        for (int im = 0; im < 4; im++) {
#pragma unroll
            for (int in = 0; in < 4; in++) {
                int r0 = mbase + im * 16 + gr;
                int c0 = nbase + in * 8 + gc;
                float b0 = bias[bn * 128 + c0], b1 = bias[bn * 128 + c0 + 1];
                ts[r0 * 129 + c0]           = acc[im][in][0] + b0;
                ts[r0 * 129 + c0 + 1]       = acc[im][in][1] + b1;
                ts[(r0 + 8) * 129 + c0]     = acc[im][in][2] + b0;
                ts[(r0 + 8) * 129 + c0 + 1] = acc[im][in][3] + b1;
            }
        }
        __syncthreads();
        const int b = (bm * 128) >> 11;
        const int sbase = (bm * 128) & (SS - 1);
#pragma unroll
        for (int hr = 0; hr < 16; hr++) {
            int hl = warp * 16 + hr;                         // local h row 0..127
            size_t obase = ((size_t)b * HH + bn * 128 + hl) * SS + sbase;
#pragma unroll
            for (int pass = 0; pass < 2; pass++) {
                int sl = pass * 64 + lane * 2;
                bf162 h2, l2;
                split2(ts[sl * 129 + hl], ts[(sl + 1) * 129 + hl], h2, l2);
                *reinterpret_cast<bf162*>(&g_vthi[obase + sl]) = h2;
                *reinterpret_cast<bf162*>(&g_vtlo[obase + sl]) = l2;
            }
        }
    }
}

// ---------------- Stage 2: scores = q k^T * scale + attn_mask + pw*prosody ----------------
__global__ __launch_bounds__(256, 2) void scores_kernel(const float* __restrict__ am,
                                                        const float* __restrict__ pm,
                                                        const float* __restrict__ pwp) {
    extern __shared__ char sm[];
    const int b = blockIdx.z, bm = blockIdx.y, bn = blockIdx.x;

    float acc[4][4][4];
    ZERO_ACC(acc);
    const size_t ao = (size_t)(b * SS + bm * 128) * HH;
    const size_t bo = (size_t)(b * SS + bn * 128) * HH;
    gemm_core(g_qhi + ao, g_qlo + ao, HH, g_khi + bo, g_klo + bo, HH, HH, sm, acc);

    const float pw = __ldg(pwp);
    const float scale = 0.03125f;   // 1/sqrt(1024)
    const int lane = threadIdx.x & 31;
    const int warp = threadIdx.x >> 5;
    const int mbase = (warp >> 2) * 64;
    const int nbase = (warp & 3) * 32;
    const int gr = lane >> 2;
    const int gc = (lane & 3) << 1;

#pragma unroll
    for (int im = 0; im < 4; im++) {
#pragma unroll
        for (int in = 0; in < 4; in++) {
            int row = bm * 128 + mbase + im * 16 + gr;
            int col = bn * 128 + nbase + in * 8 + gc;
#pragma unroll
            for (int half = 0; half < 2; half++) {
                int r = row + half * 8;
                size_t off = ((size_t)b * SS + r) * SS + col;
                float2 amv = *reinterpret_cast<const float2*>(&am[off]);
                float2 pmv = *reinterpret_cast<const float2*>(&pm[off]);
                float v0 = fmaf(acc[im][in][half * 2 + 0], scale, fmaf(pw, pmv.x, amv.x));
                float v1 = fmaf(acc[im][in][half * 2 + 1], scale, fmaf(pw, pmv.y, amv.y));
                *reinterpret_cast<float2*>(&g_s[off]) = make_float2(v0, v1);
            }
        }
    }
}

// ---------------- Stage 3: row softmax -> bf16 hi/lo prob planes ----------------
__global__ __launch_bounds__(256) void softmax_kernel() {
    const size_t rid = blockIdx.x;
    const float* row = g_s + rid * SS;
    const int tid = threadIdx.x;
    const int lane = tid & 31;
    const int warp = tid >> 5;
    const float4* rv = reinterpret_cast<const float4*>(row);
    float4 a = rv[tid];
    float4 c = rv[tid + 256];

    float m = fmaxf(fmaxf(fmaxf(a.x, a.y), fmaxf(a.z, a.w)),
                    fmaxf(fmaxf(c.x, c.y), fmaxf(c.z, c.w)));
#pragma unroll
    for (int o = 16; o > 0; o >>= 1) m = fmaxf(m, __shfl_xor_sync(0xffffffffu, m, o));
    __shared__ float smax[8], ssum[8];
    if (lane == 0) smax[warp] = m;
    __syncthreads();
    m = smax[0];
#pragma unroll
    for (int w = 1; w < 8; w++) m = fmaxf(m, smax[w]);

    a.x = fast_exp(a.x - m); a.y = fast_exp(a.y - m);
    a.z = fast_exp(a.z - m); a.w = fast_exp(a.w - m);
    c.x = fast_exp(c.x - m); c.y = fast_exp(c.y - m);
    c.z = fast_exp(c.z - m); c.w = fast_exp(c.w - m);
    float s = a.x + a.y + a.z + a.w + c.x + c.y + c.z + c.w;
#pragma unroll
    for (int o = 16; o > 0; o >>= 1) s += __shfl_xor_sync(0xffffffffu, s, o);
    if (lane == 0) ssum[warp] = s;
    __syncthreads();
    s = ssum[0];
#pragma unroll
    for (int w = 1; w < 8; w++) s += ssum[w];
    const float inv = 1.0f / s;

    bf162* ph = reinterpret_cast<bf162*>(g_phi);
    bf162* pl = reinterpret_cast<bf162*>(g_plo);
    size_t base = rid * (SS / 2) + tid * 2;
    bf162 h2, l2;
    split2(a.x * inv, a.y * inv, h2, l2); ph[base] = h2;       pl[base] = l2;
    split2(a.z * inv, a.w * inv, h2, l2); ph[base + 1] = h2;   pl[base + 1] = l2;
    split2(c.x * inv, c.y * inv, h2, l2); ph[base + 512] = h2; pl[base + 512] = l2;
    split2(c.z * inv, c.w * inv, h2, l2); ph[base + 513] = h2; pl[base + 513] = l2;
}

// ---------------- Stage 4: context = probs @ v ----------------
__global__ __launch_bounds__(256, 2) void pv_kernel(float* __restrict__ out) {
    extern __shared__ char sm[];
    const int b = blockIdx.z, bm = blockIdx.y, bn = blockIdx.x;

    float acc[4][4][4];
    ZERO_ACC(acc);
    const size_t ao = (size_t)(b * SS + bm * 128) * SS;
    const size_t bo = ((size_t)b * HH + bn * 128) * SS;
    gemm_core(g_phi + ao, g_plo + ao, SS, g_vthi + bo, g_vtlo + bo, SS, SS, sm, acc);

    const int lane = threadIdx.x & 31;
    const int warp = threadIdx.x >> 5;
    const int mbase = (warp >> 2) * 64;
    const int nbase = (warp & 3) * 32;
    const int gr = lane >> 2;
    const int gc = (lane & 3) << 1;

#pragma unroll
    for (int im = 0; im < 4; im++) {
#pragma unroll
        for (int in = 0; in < 4; in++) {
            int row = bm * 128 + mbase + im * 16 + gr;
            int col = bn * 128 + nbase + in * 8 + gc;
            size_t o0 = ((size_t)b * SS + row) * HH + col;
            size_t o1 = ((size_t)b * SS + row + 8) * HH + col;
            *reinterpret_cast<float2*>(&out[o0]) = make_float2(acc[im][in][0], acc[im][in][1]);
            *reinterpret_cast<float2*>(&out[o1]) = make_float2(acc[im][in][2], acc[im][in][3]);
        }
    }
}

// ---------------- launch ----------------
extern "C" void kernel_launch(void* const* d_in, const int* in_sizes, int n_in,
                              void* d_out, int out_size) {
    (void)in_sizes; (void)n_in; (void)out_size;
    const float* X  = (const float*)d_in[0];
    const float* am = (const float*)d_in[1];
    const float* pm = (const float*)d_in[2];
    const float* Wq = (const float*)d_in[3];
    const float* bq = (const float*)d_in[4];
    const float* Wk = (const float*)d_in[5];
    const float* bk = (const float*)d_in[6];
    const float* Wv = (const float*)d_in[7];
    const float* bv = (const float*)d_in[8];
    const float* pw = (const float*)d_in[9];
    float* out = (float*)d_out;

    cudaFuncSetAttribute(qkv_kernel,    cudaFuncAttributeMaxDynamicSharedMemorySize, SMEM_BYTES);
    cudaFuncSetAttribute(scores_kernel, cudaFuncAttributeMaxDynamicSharedMemorySize, SMEM_BYTES);
    cudaFuncSetAttribute(pv_kernel,     cudaFuncAttributeMaxDynamicSharedMemorySize, SMEM_BYTES);

    // resolve device-global plane addresses (host-side symbol lookup not needed: kernels
    // reference the globals directly; conversion kernels get raw pointers via kernels' own refs)
    {
        // X planes: 8M floats -> 2M float4
        int n4 = (BB * SS * HH) / 4;
        // obtain device pointers to the __device__ arrays for the cvt kernel
        bf162* xhi2; bf162* xlo2; bf162* whi2; bf162* wlo2;
        cudaGetSymbolAddress((void**)&xhi2, g_xhi);
        cudaGetSymbolAddress((void**)&xlo2, g_xlo);
        cudaGetSymbolAddress((void**)&whi2, g_whi);
        cudaGetSymbolAddress((void**)&wlo2, g_wlo);
        cvt_kernel<<<(n4 + 255) / 256, 256>>>((const float4*)X, xhi2, xlo2, n4);
        // W planes: Wq|Wk|Wv are three separate inputs -> three sub-launches into one array
        int w4 = (HH * HH) / 4;
        cvt_kernel<<<(w4 + 255) / 256, 256>>>((const float4*)Wq, whi2,                 wlo2,                 w4);
        cvt_kernel<<<(w4 + 255) / 256, 256>>>((const float4*)Wk, whi2 + (size_t)HH*HH/2, wlo2 + (size_t)HH*HH/2, w4);
        cvt_kernel<<<(w4 + 255) / 256, 256>>>((const float4*)Wv, whi2 + (size_t)HH*HH,   wlo2 + (size_t)HH*HH,   w4);
    }

    qkv_kernel<<<dim3(HH / 128, (BB * SS) / 128, 3), 256, SMEM_BYTES>>>(bq, bk, bv);
    scores_kernel<<<dim3(SS / 128, SS / 128, BB), 256, SMEM_BYTES>>>(am, pm, pw);
    softmax_kernel<<<BB * SS, 256>>>();
    pv_kernel<<<dim3(HH / 128, SS / 128, BB), 256, SMEM_BYTES>>>(out);
}

// round 12
// speedup vs baseline: 1.2701x; 1.2676x over previous
#include <cuda_runtime.h>
#include <cuda_bf16.h>
#include <cstdint>

#define BB 4
#define SS 2048
#define HH 1024

typedef __nv_bfloat16  bf16;
typedef __nv_bfloat162 bf162;

// ---------------- scratch (static device globals; no allocation) ----------------
__device__ __align__(256) bf16 g_xhi[(size_t)BB*SS*HH], g_xlo[(size_t)BB*SS*HH];
__device__ __align__(256) bf16 g_whi[(size_t)3*HH*HH],  g_wlo[(size_t)3*HH*HH];
__device__ __align__(256) bf16 g_qhi[(size_t)BB*SS*HH], g_qlo[(size_t)BB*SS*HH];
__device__ __align__(256) bf16 g_khi[(size_t)BB*SS*HH], g_klo[(size_t)BB*SS*HH];
__device__ __align__(256) bf16 g_vthi[(size_t)BB*HH*SS],g_vtlo[(size_t)BB*HH*SS];
__device__ __align__(256) float g_s[(size_t)BB*SS*SS];
__device__ __align__(256) bf16 g_phi[(size_t)BB*SS*SS], g_plo[(size_t)BB*SS*SS];

// ---------------- low-level helpers ----------------
static __device__ __forceinline__ void mma_bf16(float* d, const uint32_t* a, const uint32_t* b) {
    asm volatile(
        "mma.sync.aligned.m16n8k16.row.col.f32.bf16.bf16.f32 "
        "{%0,%1,%2,%3}, {%4,%5,%6,%7}, {%8,%9}, {%0,%1,%2,%3};\n"
        : "+f"(d[0]), "+f"(d[1]), "+f"(d[2]), "+f"(d[3])
        : "r"(a[0]), "r"(a[1]), "r"(a[2]), "r"(a[3]), "r"(b[0]), "r"(b[1]));
}

static __device__ __forceinline__ uint32_t smem_u32(const void* p) {
    return (uint32_t)__cvta_generic_to_shared(p);
}
static __device__ __forceinline__ void cp16(uint32_t dst, const void* src) {
    asm volatile("cp.async.cg.shared.global [%0], [%1], 16;\n" :: "r"(dst), "l"(src));
}
static __device__ __forceinline__ void cp_commit() { asm volatile("cp.async.commit_group;\n"); }
template <int N>
static __device__ __forceinline__ void cp_wait() {
    asm volatile("cp.async.wait_group %0;\n" :: "n"(N));
}
static __device__ __forceinline__ void ldm_x4(uint32_t* r, uint32_t addr) {
    asm volatile("ldmatrix.sync.aligned.m8n8.x4.shared.b16 {%0,%1,%2,%3}, [%4];\n"
        : "=r"(r[0]), "=r"(r[1]), "=r"(r[2]), "=r"(r[3]) : "r"(addr));
}
static __device__ __forceinline__ void ldm_x2(uint32_t* r, uint32_t addr) {
    asm volatile("ldmatrix.sync.aligned.m8n8.x2.shared.b16 {%0,%1}, [%2];\n"
        : "=r"(r[0]), "=r"(r[1]) : "r"(addr));
}

static __device__ __forceinline__ void split2(float x, float y, bf162& h2, bf162& l2) {
    bf16 hx = __float2bfloat16_rn(x);
    bf16 hy = __float2bfloat16_rn(y);
    h2 = __halves2bfloat162(hx, hy);
    l2 = __halves2bfloat162(__float2bfloat16_rn(x - __bfloat162float(hx)),
                            __float2bfloat16_rn(y - __bfloat162float(hy)));
}

// fast exp via degree-5 exp2 polynomial (FMA pipe, no MUFU); rel err ~1e-7
static __device__ __forceinline__ float fast_exp(float x) {
    float t = x * 1.4426950408889634f;
    float r = rintf(t);
    float f = t - r;
    float p = 1.33336498e-3f;
    p = fmaf(p, f, 9.61597636e-3f);
    p = fmaf(p, f, 5.55036440e-2f);
    p = fmaf(p, f, 2.40226462e-1f);
    p = fmaf(p, f, 6.93147182e-1f);
    p = fmaf(p, f, 1.0f);
    int e = (int)r;
    e = e < -126 ? -126 : e;
    return p * __int_as_float((e + 127) << 23);
}

// ---------------- GEMM core: C[128,128] = A[128,K]*B[128,K]^T, bf16x3 fp32-emulated ----
// Pre-split bf16 hi/lo planes in gmem, K-contiguous. KTILE=64, XOR-swizzled 128B smem
// rows (conflict-free cp.async stores + ldmatrix reads), NS=2 double buffer, 1 sync/tile.
#define KTILE   64
#define PLANE_B 16384                 // 128 rows x 128 B
#define STAGE_B (4 * PLANE_B)         // Ahi, Alo, Bhi, Blo
#define SMEM_DYN (2 * STAGE_B)        // 131072 B

static __device__ __forceinline__ void issue_stage(
    const bf16* __restrict__ Ahi, const bf16* __restrict__ Alo, size_t lda,
    const bf16* __restrict__ Bhi, const bf16* __restrict__ Blo, size_t ldb,
    int k0, uint32_t sb, int tid) {
#pragma unroll
    for (int pl = 0; pl < 4; pl++) {
        const bf16* g = (pl == 0) ? Ahi : (pl == 1) ? Alo : (pl == 2) ? Bhi : Blo;
        const size_t ld = (pl < 2) ? lda : ldb;
        const uint32_t pb = sb + pl * PLANE_B;
#pragma unroll
        for (int j = 0; j < 4; j++) {
            int idx = j * 256 + tid;         // 0..1023 chunks per plane
            int row = idx >> 3;              // 128 rows
            int ch  = idx & 7;               // 8 x 16B chunks per 128B row
            cp16(pb + row * 128 + ((ch ^ (row & 7)) << 4),
                 g + (size_t)row * ld + k0 + ch * 8);
        }
    }
    cp_commit();
}

static __device__ void gemm_core(
    const bf16* __restrict__ Ahi, const bf16* __restrict__ Alo, size_t lda,
    const bf16* __restrict__ Bhi, const bf16* __restrict__ Blo, size_t ldb,
    int n, char* sm, float acc[4][4][4]) {
    const int tid  = threadIdx.x;
    const int lane = tid & 31;
    const int warp = tid >> 5;
    const int mbase = (warp >> 2) * 64;     // 2 warps in M
    const int nbase = (warp & 3) * 32;      // 4 warps in N
    const uint32_t s0 = smem_u32(sm);

    const uint32_t sw    = (uint32_t)(lane & 7);        // XOR swizzle key (row&7 == lane&7)
    const uint32_t a_row = (uint32_t)(mbase + (lane & 15));
    const uint32_t a_hb  = (uint32_t)(lane >> 4);       // k-half select for ldm_x4
    const uint32_t b_row = (uint32_t)(nbase + (lane & 7));
    const uint32_t b_hb  = (uint32_t)((lane >> 3) & 1); // k-half select for ldm_x2

    issue_stage(Ahi, Alo, lda, Bhi, Blo, ldb, 0, s0, tid);

    for (int it = 0; it < n; ++it) {
        cp_wait<0>();
        __syncthreads();
        if (it + 1 < n)
            issue_stage(Ahi, Alo, lda, Bhi, Blo, ldb, (it + 1) * KTILE,
                        s0 + (uint32_t)((it + 1) & 1) * STAGE_B, tid);
        const uint32_t st = s0 + (uint32_t)(it & 1) * STAGE_B;
#pragma unroll
        for (int kk = 0; kk < 4; ++kk) {
            uint32_t bh[4][2], bl[4][2];
            const uint32_t bch = (uint32_t)kk * 2 + b_hb;
            const uint32_t bsw = (bch ^ sw) << 4;
#pragma unroll
            for (int in = 0; in < 4; in++) {
                uint32_t off = (b_row + in * 8) * 128 + bsw;
                ldm_x2(bh[in], st + 2 * PLANE_B + off);
                ldm_x2(bl[in], st + 3 * PLANE_B + off);
            }
            const uint32_t ach = (uint32_t)kk * 2 + a_hb;
            const uint32_t asw = (ach ^ sw) << 4;
#pragma unroll
            for (int im = 0; im < 4; im++) {
                uint32_t off = (a_row + im * 16) * 128 + asw;
                uint32_t ah[4], al[4];
                ldm_x4(ah, st + 0 * PLANE_B + off);
                ldm_x4(al, st + 1 * PLANE_B + off);
#pragma unroll
                for (int in = 0; in < 4; in++) {
                    mma_bf16(acc[im][in], ah, bh[in]);   // hi*hi
                    mma_bf16(acc[im][in], ah, bl[in]);   // hi*lo
                    mma_bf16(acc[im][in], al, bh[in]);   // lo*hi
                }
            }
        }
    }
    __syncthreads();   // smem safe for epilogue reuse
}

#define ZERO_ACC(acc) do {                                   \
    _Pragma("unroll") for (int _i = 0; _i < 4; _i++)         \
    _Pragma("unroll") for (int _j = 0; _j < 4; _j++)         \
    _Pragma("unroll") for (int _r = 0; _r < 4; _r++)         \
        acc[_i][_j][_r] = 0.0f;                              \
} while (0)

// ---------------- Stage 0: fp32 -> bf16 hi/lo plane conversion ----------------
__global__ __launch_bounds__(256) void cvt_kernel(const float4* __restrict__ src,
                                                  bf162* __restrict__ hi,
                                                  bf162* __restrict__ lo, int n4) {
    int i = blockIdx.x * blockDim.x + threadIdx.x;
    if (i < n4) {
        float4 f = src[i];
        bf162 h0, l0, h1, l1;
        split2(f.x, f.y, h0, l0);
        split2(f.z, f.w, h1, l1);
        hi[i * 2] = h0; hi[i * 2 + 1] = h1;
        lo[i * 2] = l0; lo[i * 2 + 1] = l1;
    }
}

// ---------------- Stage 1: fused QKV projection ----------------
// grid = (8, 64, 3). z selects {q,k,v}. v transposed via smem -> coalesced plane stores.
__global__ __launch_bounds__(256, 1) void qkv_kernel(const float* __restrict__ bq,
                                                     const float* __restrict__ bk,
                                                     const float* __restrict__ bv) {
    extern __shared__ char sm[];
    const int z = blockIdx.z, bm = blockIdx.y, bn = blockIdx.x;
    const float* bias = (z == 0) ? bq : ((z == 1) ? bk : bv);

    float acc[4][4][4];
    ZERO_ACC(acc);
    gemm_core(g_xhi + (size_t)bm * 128 * HH, g_xlo + (size_t)bm * 128 * HH, HH,
              g_whi + (size_t)z * HH * HH + (size_t)bn * 128 * HH,
              g_wlo + (size_t)z * HH * HH + (size_t)bn * 128 * HH, HH,
              HH / KTILE, sm, acc);

    const int lane = threadIdx.x & 31;
    const int warp = threadIdx.x >> 5;
    const int mbase = (warp >> 2) * 64;
    const int nbase = (warp & 3) * 32;
    const int gr = lane >> 2;
    const int gc = (lane & 3) << 1;

    if (z < 2) {
        bf16* ohi = (z == 0) ? g_qhi : g_khi;
        bf16* olo = (z == 0) ? g_qlo : g_klo;
#pragma unroll
        for (int im = 0; im < 4; im++) {
#pragma unroll
            for (int in = 0; in < 4; in++) {
                int row = bm * 128 + mbase + im * 16 + gr;
                int col = bn * 128 + nbase + in * 8 + gc;
                float b0 = bias[col], b1 = bias[col + 1];
                bf162 h2, l2;
                split2(acc[im][in][0] + b0, acc[im][in][1] + b1, h2, l2);
                *reinterpret_cast<bf162*>(&ohi[(size_t)row * HH + col]) = h2;
                *reinterpret_cast<bf162*>(&olo[(size_t)row * HH + col]) = l2;
                split2(acc[im][in][2] + b0, acc[im][in][3] + b1, h2, l2);
                *reinterpret_cast<bf162*>(&ohi[(size_t)(row + 8) * HH + col]) = h2;
                *reinterpret_cast<bf162*>(&olo[(size_t)(row + 8) * HH + col]) = l2;
            }
        }
    } else {
        // transpose v tile through smem, then coalesced hi/lo stores into [b][h][s] planes
        float* ts = reinterpret_cast<float*>(sm);   // 128 x 129 fp32 = 66048 B <= SMEM_DYN
#pragma unroll
        for (int im = 0; im < 4; im++) {
#pragma unroll
            for (int in = 0; in < 4; in++) {
                int r0 = mbase + im * 16 + gr;
                int c0 = nbase + in * 8 + gc;
                float b0 = bias[bn * 128 + c0], b1 = bias[bn * 128 + c0 + 1];
                ts[r0 * 129 + c0]           = acc[im][in][0] + b0;
                ts[r0 * 129 + c0 + 1]       = acc[im][in][1] + b1;
                ts[(r0 + 8) * 129 + c0]     = acc[im][in][2] + b0;
                ts[(r0 + 8) * 129 + c0 + 1] = acc[im][in][3] + b1;
            }
        }
        __syncthreads();
        const int b = (bm * 128) >> 11;
        const int sbase = (bm * 128) & (SS - 1);
#pragma unroll
        for (int hr = 0; hr < 16; hr++) {
            int hl = warp * 16 + hr;                         // local h row 0..127
            size_t obase = ((size_t)b * HH + bn * 128 + hl) * SS + sbase;
#pragma unroll
            for (int pass = 0; pass < 2; pass++) {
                int sl = pass * 64 + lane * 2;
                bf162 h2, l2;
                split2(ts[sl * 129 + hl], ts[(sl + 1) * 129 + hl], h2, l2);
                *reinterpret_cast<bf162*>(&g_vthi[obase + sl]) = h2;
                *reinterpret_cast<bf162*>(&g_vtlo[obase + sl]) = l2;
            }
        }
    }
}

// ---------------- Stage 2: scores = q k^T * scale + attn_mask + pw*prosody ----------
__global__ __launch_bounds__(256, 1) void scores_kernel(const float* __restrict__ am,
                                                        const float* __restrict__ pm,
                                                        const float* __restrict__ pwp) {
    extern __shared__ char sm[];
    const int b = blockIdx.z, bm = blockIdx.y, bn = blockIdx.x;

    float acc[4][4][4];
    ZERO_ACC(acc);
    const size_t ao = ((size_t)b * SS + bm * 128) * HH;
    const size_t bo = ((size_t)b * SS + bn * 128) * HH;
    gemm_core(g_qhi + ao, g_qlo + ao, HH, g_khi + bo, g_klo + bo, HH,
              HH / KTILE, sm, acc);

    const float pw = __ldg(pwp);
    const float scale = 0.03125f;   // 1/sqrt(1024)
    const int lane = threadIdx.x & 31;
    const int warp = threadIdx.x >> 5;
    const int mbase = (warp >> 2) * 64;
    const int nbase = (warp & 3) * 32;
    const int gr = lane >> 2;
    const int gc = (lane & 3) << 1;

#pragma unroll
    for (int im = 0; im < 4; im++) {
#pragma unroll
        for (int in = 0; in < 4; in++) {
            int row = bm * 128 + mbase + im * 16 + gr;
            int col = bn * 128 + nbase + in * 8 + gc;
#pragma unroll
            for (int half = 0; half < 2; half++) {
                int r = row + half * 8;
                size_t off = ((size_t)b * SS + r) * SS + col;
                float2 amv = *reinterpret_cast<const float2*>(&am[off]);
                float2 pmv = *reinterpret_cast<const float2*>(&pm[off]);
                float v0 = fmaf(acc[im][in][half * 2 + 0], scale, fmaf(pw, pmv.x, amv.x));
                float v1 = fmaf(acc[im][in][half * 2 + 1], scale, fmaf(pw, pmv.y, amv.y));
                *reinterpret_cast<float2*>(&g_s[off]) = make_float2(v0, v1);
            }
        }
    }
}

// ---------------- Stage 3: row softmax -> bf16 hi/lo prob planes ----------------
__global__ __launch_bounds__(256) void softmax_kernel() {
    const size_t rid = blockIdx.x;
    const float* row = g_s + rid * SS;
    const int tid = threadIdx.x;
    const int lane = tid & 31;
    const int warp = tid >> 5;
    const float4* rv = reinterpret_cast<const float4*>(row);
    float4 a = rv[tid];
    float4 c = rv[tid + 256];

    float m = fmaxf(fmaxf(fmaxf(a.x, a.y), fmaxf(a.z, a.w)),
                    fmaxf(fmaxf(c.x, c.y), fmaxf(c.z, c.w)));
#pragma unroll
    for (int o = 16; o > 0; o >>= 1) m = fmaxf(m, __shfl_xor_sync(0xffffffffu, m, o));
    __shared__ float smax[8], ssum[8];
    if (lane == 0) smax[warp] = m;
    __syncthreads();
    m = smax[0];
#pragma unroll
    for (int w = 1; w < 8; w++) m = fmaxf(m, smax[w]);

    a.x = fast_exp(a.x - m); a.y = fast_exp(a.y - m);
    a.z = fast_exp(a.z - m); a.w = fast_exp(a.w - m);
    c.x = fast_exp(c.x - m); c.y = fast_exp(c.y - m);
    c.z = fast_exp(c.z - m); c.w = fast_exp(c.w - m);
    float s = a.x + a.y + a.z + a.w + c.x + c.y + c.z + c.w;
#pragma unroll
    for (int o = 16; o > 0; o >>= 1) s += __shfl_xor_sync(0xffffffffu, s, o);
    if (lane == 0) ssum[warp] = s;
    __syncthreads();
    s = ssum[0];
#pragma unroll
    for (int w = 1; w < 8; w++) s += ssum[w];
    const float inv = 1.0f / s;

    bf162* ph = reinterpret_cast<bf162*>(g_phi);
    bf162* pl = reinterpret_cast<bf162*>(g_plo);
    size_t base = rid * (SS / 2) + tid * 2;
    bf162 h2, l2;
    split2(a.x * inv, a.y * inv, h2, l2); ph[base] = h2;       pl[base] = l2;
    split2(a.z * inv, a.w * inv, h2, l2); ph[base + 1] = h2;   pl[base + 1] = l2;
    split2(c.x * inv, c.y * inv, h2, l2); ph[base + 512] = h2; pl[base + 512] = l2;
    split2(c.z * inv, c.w * inv, h2, l2); ph[base + 513] = h2; pl[base + 513] = l2;
}

// ---------------- Stage 4: context = probs @ v ----------------
__global__ __launch_bounds__(256, 1) void pv_kernel(float* __restrict__ out) {
    extern __shared__ char sm[];
    const int b = blockIdx.z, bm = blockIdx.y, bn = blockIdx.x;

    float acc[4][4][4];
    ZERO_ACC(acc);
    const size_t ao = ((size_t)b * SS + bm * 128) * SS;
    const size_t bo = ((size_t)b * HH + bn * 128) * SS;
    gemm_core(g_phi + ao, g_plo + ao, SS, g_vthi + bo, g_vtlo + bo, SS,
              SS / KTILE, sm, acc);

    const int lane = threadIdx.x & 31;
    const int warp = threadIdx.x >> 5;
    const int mbase = (warp >> 2) * 64;
    const int nbase = (warp & 3) * 32;
    const int gr = lane >> 2;
    const int gc = (lane & 3) << 1;

#pragma unroll
    for (int im = 0; im < 4; im++) {
#pragma unroll
        for (int in = 0; in < 4; in++) {
            int row = bm * 128 + mbase + im * 16 + gr;
            int col = bn * 128 + nbase + in * 8 + gc;
            size_t o0 = ((size_t)b * SS + row) * HH + col;
            size_t o1 = ((size_t)b * SS + row + 8) * HH + col;
            *reinterpret_cast<float2*>(&out[o0]) = make_float2(acc[im][in][0], acc[im][in][1]);
            *reinterpret_cast<float2*>(&out[o1]) = make_float2(acc[im][in][2], acc[im][in][3]);
        }
    }
}

// ---------------- launch ----------------
extern "C" void kernel_launch(void* const* d_in, const int* in_sizes, int n_in,
                              void* d_out, int out_size) {
    (void)in_sizes; (void)n_in; (void)out_size;
    const float* X  = (const float*)d_in[0];
    const float* am = (const float*)d_in[1];
    const float* pm = (const float*)d_in[2];
    const float* Wq = (const float*)d_in[3];
    const float* bq = (const float*)d_in[4];
    const float* Wk = (const float*)d_in[5];
    const float* bk = (const float*)d_in[6];
    const float* Wv = (const float*)d_in[7];
    const float* bv = (const float*)d_in[8];
    const float* pw = (const float*)d_in[9];
    float* out = (float*)d_out;

    cudaFuncSetAttribute(qkv_kernel,    cudaFuncAttributeMaxDynamicSharedMemorySize, SMEM_DYN);
    cudaFuncSetAttribute(scores_kernel, cudaFuncAttributeMaxDynamicSharedMemorySize, SMEM_DYN);
    cudaFuncSetAttribute(pv_kernel,     cudaFuncAttributeMaxDynamicSharedMemorySize, SMEM_DYN);

    {
        bf162 *xhi2, *xlo2, *whi2, *wlo2;
        cudaGetSymbolAddress((void**)&xhi2, g_xhi);
        cudaGetSymbolAddress((void**)&xlo2, g_xlo);
        cudaGetSymbolAddress((void**)&whi2, g_whi);
        cudaGetSymbolAddress((void**)&wlo2, g_wlo);
        int n4 = (BB * SS * HH) / 4;
        cvt_kernel<<<(n4 + 255) / 256, 256>>>((const float4*)X, xhi2, xlo2, n4);
        int w4 = (HH * HH) / 4;
        cvt_kernel<<<(w4 + 255) / 256, 256>>>((const float4*)Wq, whi2, wlo2, w4);
        cvt_kernel<<<(w4 + 255) / 256, 256>>>((const float4*)Wk,
            whi2 + (size_t)HH * HH / 2, wlo2 + (size_t)HH * HH / 2, w4);
        cvt_kernel<<<(w4 + 255) / 256, 256>>>((const float4*)Wv,
            whi2 + (size_t)HH * HH, wlo2 + (size_t)HH * HH, w4);
    }

    qkv_kernel<<<dim3(HH / 128, (BB * SS) / 128, 3), 256, SMEM_DYN>>>(bq, bk, bv);
    scores_kernel<<<dim3(SS / 128, SS / 128, BB), 256, SMEM_DYN>>>(am, pm, pw);
    softmax_kernel<<<BB * SS, 256>>>();
    pv_kernel<<<dim3(HH / 128, SS / 128, BB), 256, SMEM_DYN>>>(out);
}